// round 11
// baseline (speedup 1.0000x reference)
#include <cuda_runtime.h>
#include <cuda_fp16.h>
#include <cstdint>

// ---------------------------------------------------------------------------
// GCN via mma.sync fp16 GEMMs (fp32 accumulate).
//   GEMM1: H^T[256][32768] = W^T @ X^T  -> fp16
//   GEMM2: Out[b] = adj @ H_b           -> fp32
// R11: GEMMs = R8 config (measured best; mma.sync issue-rate floor ~83%
//      reached). cvt_all rewritten for MLP=8 batched loads to approach the
//      48MB traffic floor (~6us).
// ---------------------------------------------------------------------------

#define N_NODES 512
#define N_BATCH 64
#define D_IN    256
#define D_OUT   256
#define M_ALL   (N_NODES * N_BATCH)   // 32768

#define BM 128
#define BN 128
#define BKB 64                        // fp16 k per stage
#define NTHREADS 256
#define S_STAGES 3
#define PITCHB 144                    // 128B row + 16B pad -> ldsm conflict-free
#define TILEB (128 * PITCHB)          // 18432 per matrix
#define STAGEB (2 * TILEB)            // 36864
#define SMEM_TOTAL (S_STAGES * STAGEB) // 110592
#define OFF_A 0
#define OFF_B TILEB

// device scratch
__device__ __half g_xh[(size_t)M_ALL * D_IN];
__device__ __half g_wth[D_OUT * D_IN];
__device__ __half g_adjh[N_NODES * N_NODES];
__device__ __half g_h[(size_t)D_OUT * M_ALL];

// ---------------- helpers ----------------
__device__ __forceinline__ uint32_t smem_u32(const void* p) {
    uint32_t a;
    asm("{ .reg .u64 t; cvta.to.shared.u64 t, %1; cvt.u32.u64 %0, t; }" : "=r"(a) : "l"(p));
    return a;
}
__device__ __forceinline__ void cp16(uint32_t dst, const void* src) {
    asm volatile("cp.async.cg.shared.global [%0], [%1], 16;" :: "r"(dst), "l"(src) : "memory");
}
__device__ __forceinline__ void cp_commit() {
    asm volatile("cp.async.commit_group;" ::: "memory");
}
template <int N>
__device__ __forceinline__ void cp_wait() {
    asm volatile("cp.async.wait_group %0;" :: "n"(N) : "memory");
}
__device__ __forceinline__ void ldsm_x4(uint32_t* r, uint32_t addr) {
    asm volatile("ldmatrix.sync.aligned.m8n8.x4.shared.b16 {%0,%1,%2,%3}, [%4];"
                 : "=r"(r[0]), "=r"(r[1]), "=r"(r[2]), "=r"(r[3]) : "r"(addr));
}
__device__ __forceinline__ void mma_f16(float* c, const uint32_t* a, const uint32_t* b) {
    asm volatile(
        "mma.sync.aligned.m16n8k16.row.col.f32.f16.f16.f32 "
        "{%0,%1,%2,%3}, {%4,%5,%6,%7}, {%8,%9}, {%0,%1,%2,%3};"
        : "+f"(c[0]), "+f"(c[1]), "+f"(c[2]), "+f"(c[3])
        : "r"(a[0]), "r"(a[1]), "r"(a[2]), "r"(a[3]), "r"(b[0]), "r"(b[1]));
}
__device__ __forceinline__ uint2 cvt_f4(float4 a) {
    __half2 h0 = __float22half2_rn(make_float2(a.x, a.y));
    __half2 h1 = __float22half2_rn(make_float2(a.z, a.w));
    return make_uint2(*(uint32_t*)&h0, *(uint32_t*)&h1);
}

// ---------------- convert: x (MLP=8 batched) ----------------
// n8 = 1048576 float4-pairs? We process in units of float4: 2097152 float4.
// Each thread: 8 float4 loads in flight, 4 uint4 stores. grid 1024 x 256:
// 262144 threads x 8 float4 = 2097152 float4 per pass (exactly one pass).
__global__ __launch_bounds__(256) void cvt_x(const float* __restrict__ x,
                                             __half* __restrict__ xh) {
    const size_t t = (size_t)blockIdx.x * 256 + threadIdx.x;
    const float4* src = (const float4*)x;
    // 8 independent loads, strided so each warp's batch is contiguous-ish
    float4 v[8];
#pragma unroll
    for (int j = 0; j < 8; j++) v[j] = src[t * 8 + j];
    uint4 o[4];
#pragma unroll
    for (int j = 0; j < 4; j++) {
        uint2 a = cvt_f4(v[2 * j]);
        uint2 b = cvt_f4(v[2 * j + 1]);
        o[j] = make_uint4(a.x, a.y, b.x, b.y);
    }
#pragma unroll
    for (int j = 0; j < 4; j++) ((uint4*)xh)[t * 4 + j] = o[j];
}

// ---------------- convert: adj + w^T (small) ----------------
// blocks [0,32): adj | [32,288): w transpose
__global__ __launch_bounds__(256) void cvt_small(const float* __restrict__ adj,
                                                 const float* __restrict__ w,
                                                 __half* __restrict__ adjh,
                                                 __half* __restrict__ wth) {
    const int b = blockIdx.x;
    if (b < 32) {
        const size_t t = (size_t)b * 256 + threadIdx.x;   // 8192 threads
        const float4* src = (const float4*)adj;           // 65536 float4
        float4 v[8];
#pragma unroll
        for (int j = 0; j < 8; j++) v[j] = src[t * 8 + j];
#pragma unroll
        for (int j = 0; j < 4; j++) {
            uint2 a = cvt_f4(v[2 * j]);
            uint2 c = cvt_f4(v[2 * j + 1]);
            ((uint4*)adjh)[t * 4 + j] = make_uint4(a.x, a.y, c.x, c.y);
        }
    } else {
        int o = b - 32;             // 0..255
        int i = threadIdx.x;        // 0..255
        wth[o * D_IN + i] = __float2half_rn(w[i * D_OUT + o]);
    }
}

// ---------------- main GEMM: C = A * B^T (both K-major, fp16) ----------------
template <bool HALF_OUT>
__global__ __launch_bounds__(NTHREADS, 2)
void hgemm_f16(const __half* __restrict__ A, int lda,
               const __half* __restrict__ B, int ldb, long bStride,
               __half* __restrict__ Ch, float* __restrict__ Cf,
               int ldc, long cStride, int K) {
    extern __shared__ char smem[];
    const uint32_t sb = smem_u32(smem);
    const int tid = threadIdx.x;
    const int lane = tid & 31;
    const int wid = tid >> 5;
    const int wm = (wid & 3) * 32;   // warp m offset
    const int wn = (wid >> 2) * 64;  // warp n offset

    const int m0 = blockIdx.y * BM;
    const int n0 = blockIdx.x * BN;
    const long bz = blockIdx.z;
    B += bz * bStride;

    // cp.async coords: per matrix 128 rows x 8 chunks of 16B; 4 chunks/thread
    const int cr = tid >> 3;          // base row 0..31 (+32 per j)
    const int cc = tid & 7;           // 16B chunk in row
    const uint32_t soBase = (uint32_t)(cc * 16);
    const int gcol = cc * 8;          // halves

    // ldmatrix addresses (conflict-free: PITCHB mod 128 = 16)
    const uint32_t aOff = (uint32_t)((wm + (lane & 15)) * PITCHB + ((lane >> 4) << 4));
    const uint32_t bOff = (uint32_t)((wn + ((lane >> 4) << 3) + (lane & 7)) * PITCHB +
                                     (((lane >> 3) & 1) << 4));

    float acc[2][8][4];
#pragma unroll
    for (int mt = 0; mt < 2; mt++)
#pragma unroll
        for (int nt = 0; nt < 8; nt++)
#pragma unroll
            for (int q = 0; q < 4; q++) acc[mt][nt][q] = 0.0f;

    const int NT = K / BKB;

    auto load_stage = [&](int t) {
        const uint32_t st = sb + (uint32_t)((t % S_STAGES) * STAGEB);
        const int k0 = t * BKB + gcol;
#pragma unroll
        for (int j = 0; j < 4; j++) {
            int r = cr + j * 32;
            uint32_t so = (uint32_t)(r * PITCHB) + soBase;
            cp16(st + OFF_A + so, A + (size_t)(m0 + r) * lda + k0);
            cp16(st + OFF_B + so, B + (size_t)(n0 + r) * ldb + k0);
        }
        cp_commit();
    };

    load_stage(0);
    if (NT > 1) load_stage(1);

    for (int t = 0; t < NT; t++) {
        cp_wait<1>();
        __syncthreads();

        const uint32_t st = sb + (uint32_t)((t % S_STAGES) * STAGEB);

        // A-frag double buffer across ko
        uint32_t ah[2][2][4];
#pragma unroll
        for (int mt = 0; mt < 2; mt++)
            ldsm_x4(ah[0][mt], st + OFF_A + aOff + mt * 16 * PITCHB);

#pragma unroll
        for (int ko = 0; ko < 4; ko++) {
            const int cur = ko & 1, nxt = cur ^ 1;
            if (ko < 3) {
#pragma unroll
                for (int mt = 0; mt < 2; mt++)
                    ldsm_x4(ah[nxt][mt], st + OFF_A + aOff + mt * 16 * PITCHB + (ko + 1) * 32);
            }
#pragma unroll
            for (int np = 0; np < 4; np++) {
                uint32_t bh[4];
                ldsm_x4(bh, st + OFF_B + bOff + np * 16 * PITCHB + ko * 32);
#pragma unroll
                for (int sub = 0; sub < 2; sub++)
#pragma unroll
                    for (int mt = 0; mt < 2; mt++)
                        mma_f16(acc[mt][np * 2 + sub], ah[cur][mt], bh + sub * 2);
            }
        }

        __syncthreads();
        // Commit every iteration so cp_wait<1> at iteration t implies stage t done.
        if (t + 2 < NT) {
            load_stage(t + 2);
        } else {
            cp_commit();
        }
    }

    // epilogue
    const int l4 = lane >> 2;
    const int lp = lane & 3;
#pragma unroll
    for (int mt = 0; mt < 2; mt++) {
#pragma unroll
        for (int nt = 0; nt < 8; nt++) {
            const float* c = acc[mt][nt];
            long m = m0 + wm + mt * 16 + l4;
            long n = n0 + wn + nt * 8 + lp * 2;
            if (HALF_OUT) {
                __half2 p0 = __float22half2_rn(make_float2(c[0], c[1]));
                __half2 p1 = __float22half2_rn(make_float2(c[2], c[3]));
                *(uint32_t*)(Ch + m * ldc + n) = *(uint32_t*)&p0;
                *(uint32_t*)(Ch + (m + 8) * ldc + n) = *(uint32_t*)&p1;
            } else {
                float* base = Cf + bz * cStride;
                *(float2*)(base + m * ldc + n) = make_float2(c[0], c[1]);
                *(float2*)(base + (m + 8) * ldc + n) = make_float2(c[2], c[3]);
            }
        }
    }
}

// ---------------- launch ----------------
extern "C" void kernel_launch(void* const* d_in, const int* in_sizes, int n_in,
                              void* d_out, int out_size) {
    const float* x      = (const float*)d_in[0];
    const float* weight = (const float*)d_in[2];
    const float* adj    = (const float*)d_in[3];
    float* out          = (float*)d_out;

    __half *xh, *wth, *adjh, *h;
    cudaGetSymbolAddress((void**)&xh, g_xh);
    cudaGetSymbolAddress((void**)&wth, g_wth);
    cudaGetSymbolAddress((void**)&adjh, g_adjh);
    cudaGetSymbolAddress((void**)&h, g_h);

    cudaFuncSetAttribute(hgemm_f16<true>, cudaFuncAttributeMaxDynamicSharedMemorySize, SMEM_TOTAL);
    cudaFuncSetAttribute(hgemm_f16<false>, cudaFuncAttributeMaxDynamicSharedMemorySize, SMEM_TOTAL);

    // converts: x (big, MLP=8) + small (adj, w^T)
    cvt_x<<<1024, 256>>>(x, xh);
    cvt_small<<<288, 256>>>(adj, weight, adjh, wth);

    // GEMM1: H^T = W^T @ X^T ; A=W^T [256][256], B=X [32768][256] -> H^T fp16
    {
        dim3 grid(M_ALL / BN, D_OUT / BM, 1);
        hgemm_f16<true><<<grid, NTHREADS, SMEM_TOTAL>>>(
            wth, D_IN,
            xh, D_IN, 0L,
            h, nullptr, M_ALL, 0L,
            D_IN);
    }
    // GEMM2: Out[b] = adj @ H_b ; A=adj [512][512], B=H^T col-slice b*512
    {
        dim3 grid(D_OUT / BN, N_NODES / BM, N_BATCH);
        hgemm_f16<false><<<grid, NTHREADS, SMEM_TOTAL>>>(
            adjh, N_NODES,
            h, M_ALL, (long)N_NODES,
            nullptr, out, D_OUT, (long)(N_NODES * D_OUT),
            N_NODES);
    }
}